// round 4
// baseline (speedup 1.0000x reference)
#include <cuda_runtime.h>

#define NN 50000
#define EE 800000
#define IND 128
#define EDD 16
#define HH 64
#define HH2 128
#define OUTD 8
#define NLAYER 4

// ---------------- scratch (static __device__, no allocations) ----------------
__device__ float d_ea[EE * HH];        // 204.8 MB: edge features, dst-sorted order
__device__ int   d_srcS[EE];           // src node id per sorted edge
__device__ int   d_perm[EE];           // sorted-pos -> original edge id
__device__ int   d_rowStart[NN + 1];   // CSR row offsets (by dst)
__device__ int   d_cursor[NN];         // histogram / scatter cursor
__device__ float d_h[NN * HH];         // running node state
__device__ float d_z[NN * HH];         // per-layer conv input (normalized)
__device__ int   d_is64;               // edge_index dtype flag

__device__ __forceinline__ float warpSum(float v) {
#pragma unroll
    for (int o = 16; o; o >>= 1) v += __shfl_xor_sync(0xffffffffu, v, o);
    return v;
}

// read edge_index entry i (0..2E-1) honoring detected dtype
__device__ __forceinline__ int eiAt(const void* eiv, int i) {
    if (d_is64) return (int)((const long long*)eiv)[i];
    return ((const int*)eiv)[i];
}

// ---------------- dtype probe ----------------
__global__ void detectK(const void* eiv) {
    if (threadIdx.x == 0 && blockIdx.x == 0) {
        const unsigned long long* p = (const unsigned long long*)eiv;
        int ok = 1;
#pragma unroll
        for (int i = 0; i < 8; i++)
            if (p[i] >= (unsigned long long)NN) ok = 0;
        d_is64 = ok;
    }
}

// ---------------- CSR build ----------------
__global__ void zeroK() {
    int i = blockIdx.x * blockDim.x + threadIdx.x;
    if (i < NN) d_cursor[i] = 0;
}

__global__ void histK(const void* eiv) {
    int e = blockIdx.x * blockDim.x + threadIdx.x;
    if (e < EE) {
        int d = eiAt(eiv, EE + e);
        if ((unsigned)d < (unsigned)NN) atomicAdd(&d_cursor[d], 1);
    }
}

// single-block exclusive scan of 50000 counts (1024 threads, chunked)
__global__ void scanK() {
    __shared__ int part[1024];
    int tid = threadIdx.x;
    const int CH = (NN + 1023) / 1024;   // 49
    int base = tid * CH;
    int sum = 0;
    for (int i = 0; i < CH; i++) {
        int idx = base + i;
        if (idx < NN) sum += d_cursor[idx];
    }
    part[tid] = sum;
    __syncthreads();
    for (int off = 1; off < 1024; off <<= 1) {
        int v = (tid >= off) ? part[tid - off] : 0;
        __syncthreads();
        part[tid] += v;
        __syncthreads();
    }
    int run = part[tid] - sum;           // exclusive prefix of this thread's chunk
    for (int i = 0; i < CH; i++) {
        int idx = base + i;
        if (idx < NN) {
            int cnum = d_cursor[idx];
            d_rowStart[idx] = run;
            d_cursor[idx] = run;         // scatter cursor starts at rowStart
            run += cnum;
        }
    }
    if (tid == 0) d_rowStart[NN] = part[1023];
}

__global__ void scatterK(const void* eiv) {
    int e = blockIdx.x * blockDim.x + threadIdx.x;
    if (e < EE) {
        int s = eiAt(eiv, e);
        int d = eiAt(eiv, EE + e);
        if ((unsigned)d < (unsigned)NN && (unsigned)s < (unsigned)NN) {
            int p = atomicAdd(&d_cursor[d], 1);
            d_srcS[p] = s;
            d_perm[p] = e;
        }
    }
}

// ---------------- edge encoder: d_ea[sorted] = edge_attr[perm] @ edge_W + edge_b ----------------
__global__ void eaK(const float* __restrict__ eattr,
                    const float* __restrict__ eW,
                    const float* __restrict__ eb) {
    __shared__ float Ws[EDD * HH];
    __shared__ float bs[HH];
    for (int i = threadIdx.x; i < EDD * HH; i += blockDim.x) Ws[i] = eW[i];
    if (threadIdx.x < HH) bs[threadIdx.x] = eb[threadIdx.x];
    __syncthreads();
    int lane = threadIdx.x & 31;
    int warp = (blockIdx.x * blockDim.x + threadIdx.x) >> 5;
    int nwarp = (gridDim.x * blockDim.x) >> 5;
    int c = 2 * lane;
    for (int i = warp; i < EE; i += nwarp) {
        int e = d_perm[i];
        float a = (lane < EDD) ? __ldg(&eattr[e * EDD + lane]) : 0.f;
        float c0 = bs[c], c1 = bs[c + 1];
#pragma unroll
        for (int k = 0; k < EDD; k++) {
            float ak = __shfl_sync(0xffffffffu, a, k);
            float2 w = *(const float2*)&Ws[k * HH + c];
            c0 = fmaf(ak, w.x, c0);
            c1 = fmaf(ak, w.y, c1);
        }
        *(float2*)&d_ea[i * HH + c] = make_float2(c0, c1);
    }
}

// ---------------- node encoder: d_z = x @ node_W + node_b ----------------
__global__ void nodeEncK(const float* __restrict__ x,
                         const float* __restrict__ W,
                         const float* __restrict__ b) {
    __shared__ float Ws[IND * HH];
    __shared__ float bs[HH];
    __shared__ float xs[8][IND];
    for (int i = threadIdx.x; i < IND * HH; i += blockDim.x) Ws[i] = W[i];
    if (threadIdx.x < HH) bs[threadIdx.x] = b[threadIdx.x];
    __syncthreads();
    int lane = threadIdx.x & 31, wi = threadIdx.x >> 5;
    int warp = (blockIdx.x << 3) + wi;
    int nwarp = gridDim.x << 3;
    int c = 2 * lane;
    for (int v = warp; v < NN; v += nwarp) {
        const float* xr = &x[v * IND];
        xs[wi][lane]      = xr[lane];
        xs[wi][lane + 32] = xr[lane + 32];
        xs[wi][lane + 64] = xr[lane + 64];
        xs[wi][lane + 96] = xr[lane + 96];
        __syncwarp();
        float c0 = bs[c], c1 = bs[c + 1];
#pragma unroll 8
        for (int k = 0; k < IND; k++) {
            float xk = xs[wi][k];
            float2 w = *(const float2*)&Ws[k * HH + c];
            c0 = fmaf(xk, w.x, c0);
            c1 = fmaf(xk, w.y, c1);
        }
        *(float2*)&d_z[v * HH + c] = make_float2(c0, c1);
        __syncwarp();
    }
}

// ---------------- fused GENConv layer ----------------
// warp per node: softmax-aggregate (single pass; logits = relu(.)+eps in [1e-7, ~8], exp safe),
// add root, MLP 64->128, LN+relu, MLP 128->64, optional residual into d_h.
__global__ void convK(const float* __restrict__ W1, const float* __restrict__ b1,
                      const float* __restrict__ g1, const float* __restrict__ be1,
                      const float* __restrict__ W2, const float* __restrict__ b2,
                      const float* __restrict__ tptr, int layer, int residual) {
    extern __shared__ float smemf[];
    float* W1s  = smemf;                  // 64*128
    float* W2s  = W1s + HH * HH2;         // 128*64
    float* b1s  = W2s + HH2 * HH;         // 128
    float* g1s  = b1s + HH2;              // 128
    float* be1s = g1s + HH2;              // 128
    float* b2s  = be1s + HH2;             // 64
    float* hbuf = b2s + HH;               // 8*64
    float* zbuf = hbuf + 8 * HH;          // 8*128

    for (int i = threadIdx.x; i < HH * HH2; i += blockDim.x) { W1s[i] = W1[i]; W2s[i] = W2[i]; }
    for (int i = threadIdx.x; i < HH2; i += blockDim.x) { b1s[i] = b1[i]; g1s[i] = g1[i]; be1s[i] = be1[i]; }
    if (threadIdx.x < HH) b2s[threadIdx.x] = b2[threadIdx.x];
    __syncthreads();

    float t = __ldg(&tptr[layer]);
    int lane = threadIdx.x & 31, wi = threadIdx.x >> 5;
    int warp = (blockIdx.x << 3) + wi;
    int nwarp = gridDim.x << 3;
    int c = 2 * lane;
    float* hb = &hbuf[wi * HH];
    float* zb = &zbuf[wi * HH2];

    for (int v = warp; v < NN; v += nwarp) {
        int rs = d_rowStart[v], re = d_rowStart[v + 1];
        float s0 = 0.f, s1 = 0.f, w0 = 0.f, w1 = 0.f;
        for (int e = rs; e < re; e++) {
            float2 eav = *(const float2*)&d_ea[e * HH + c];
            int u = d_srcS[e];
            float2 zu = *(const float2*)&d_z[u * HH + c];
            float m0 = fmaxf(zu.x + eav.x, 0.f) + 1e-7f;
            float m1 = fmaxf(zu.y + eav.y, 0.f) + 1e-7f;
            float p0 = __expf(m0 * t);
            float p1 = __expf(m1 * t);
            s0 += p0; s1 += p1;
            w0 = fmaf(m0, p0, w0);
            w1 = fmaf(m1, p1, w1);
        }
        float2 zv = *(const float2*)&d_z[v * HH + c];
        float h0 = w0 / (s0 + 1e-16f) + zv.x;
        float h1 = w1 / (s1 + 1e-16f) + zv.y;
        *(float2*)&hb[c] = make_float2(h0, h1);
        __syncwarp();

        // MLP1: 64 -> 128, each lane computes 4 outputs
        int o = lane * 4;
        float4 acc = *(const float4*)&b1s[o];
#pragma unroll 16
        for (int k = 0; k < HH; k++) {
            float hk = hb[k];
            float4 w = *(const float4*)&W1s[k * HH2 + o];
            acc.x = fmaf(hk, w.x, acc.x);
            acc.y = fmaf(hk, w.y, acc.y);
            acc.z = fmaf(hk, w.z, acc.z);
            acc.w = fmaf(hk, w.w, acc.w);
        }
        // LayerNorm over 128 + relu
        float mu = warpSum(acc.x + acc.y + acc.z + acc.w) * (1.f / HH2);
        float dx = acc.x - mu, dy = acc.y - mu, dz = acc.z - mu, dw = acc.w - mu;
        float var = warpSum(dx * dx + dy * dy + dz * dz + dw * dw) * (1.f / HH2);
        float inv = rsqrtf(var + 1e-5f);
        float4 zo;
        zo.x = fmaxf(fmaf(dx * inv, g1s[o + 0], be1s[o + 0]), 0.f);
        zo.y = fmaxf(fmaf(dy * inv, g1s[o + 1], be1s[o + 1]), 0.f);
        zo.z = fmaxf(fmaf(dz * inv, g1s[o + 2], be1s[o + 2]), 0.f);
        zo.w = fmaxf(fmaf(dw * inv, g1s[o + 3], be1s[o + 3]), 0.f);
        *(float4*)&zb[o] = zo;
        __syncwarp();

        // MLP2: 128 -> 64, each lane computes 2 outputs
        float a0 = b2s[c], a1 = b2s[c + 1];
#pragma unroll 16
        for (int k = 0; k < HH2; k++) {
            float zk = zb[k];
            float2 w = *(const float2*)&W2s[k * HH + c];
            a0 = fmaf(zk, w.x, a0);
            a1 = fmaf(zk, w.y, a1);
        }
        float2 outv;
        if (residual) {
            float2 hv = *(const float2*)&d_h[v * HH + c];
            outv = make_float2(hv.x + a0, hv.y + a1);
        } else {
            outv = make_float2(a0, a1);
        }
        *(float2*)&d_h[v * HH + c] = outv;
        __syncwarp();
    }
}

// ---------------- pre-norm for res+ blocks: d_z = relu(LN(d_h)) ----------------
__global__ void normReluK(const float* __restrict__ g, const float* __restrict__ b) {
    int lane = threadIdx.x & 31;
    int v = (blockIdx.x * blockDim.x + threadIdx.x) >> 5;
    if (v >= NN) return;
    int c = 2 * lane;
    float2 hv = *(const float2*)&d_h[v * HH + c];
    float mu = warpSum(hv.x + hv.y) * (1.f / HH);
    float d0 = hv.x - mu, d1 = hv.y - mu;
    float var = warpSum(d0 * d0 + d1 * d1) * (1.f / HH);
    float inv = rsqrtf(var + 1e-5f);
    float z0 = fmaxf(fmaf(d0 * inv, __ldg(&g[c]), __ldg(&b[c])), 0.f);
    float z1 = fmaxf(fmaf(d1 * inv, __ldg(&g[c + 1]), __ldg(&b[c + 1])), 0.f);
    *(float2*)&d_z[v * HH + c] = make_float2(z0, z1);
}

// ---------------- final: out = relu(LN(d_h, g0, b0)) @ lin_W + lin_b ----------------
__global__ void finalK(const float* __restrict__ g, const float* __restrict__ b,
                       const float* __restrict__ lW, const float* __restrict__ lb,
                       float* __restrict__ out) {
    __shared__ float Ws[HH * OUTD];
    __shared__ float zs[8][HH];
    for (int i = threadIdx.x; i < HH * OUTD; i += blockDim.x) Ws[i] = lW[i];
    __syncthreads();
    int lane = threadIdx.x & 31, wi = threadIdx.x >> 5;
    int warp = (blockIdx.x << 3) + wi;
    int nwarp = gridDim.x << 3;
    int c = 2 * lane;
    for (int v = warp; v < NN; v += nwarp) {
        float2 hv = *(const float2*)&d_h[v * HH + c];
        float mu = warpSum(hv.x + hv.y) * (1.f / HH);
        float d0 = hv.x - mu, d1 = hv.y - mu;
        float var = warpSum(d0 * d0 + d1 * d1) * (1.f / HH);
        float inv = rsqrtf(var + 1e-5f);
        zs[wi][c]     = fmaxf(fmaf(d0 * inv, __ldg(&g[c]),     __ldg(&b[c])),     0.f);
        zs[wi][c + 1] = fmaxf(fmaf(d1 * inv, __ldg(&g[c + 1]), __ldg(&b[c + 1])), 0.f);
        __syncwarp();
        if (lane < OUTD) {
            float acc = __ldg(&lb[lane]);
#pragma unroll
            for (int k = 0; k < HH; k++) acc = fmaf(zs[wi][k], Ws[k * OUTD + lane], acc);
            out[v * OUTD + lane] = acc;
        }
        __syncwarp();
    }
}

// ---------------- launch ----------------
extern "C" void kernel_launch(void* const* d_in, const int* in_sizes, int n_in,
                              void* d_out, int out_size) {
    const float* x     = (const float*)d_in[0];
    const float* eattr = (const float*)d_in[1];
    const float* nodeW = (const float*)d_in[2];
    const float* nodeb = (const float*)d_in[3];
    const float* edgeW = (const float*)d_in[4];
    const float* edgeb = (const float*)d_in[5];
    const float* convT = (const float*)d_in[6];
    const float* cW1   = (const float*)d_in[7];
    const float* cb1   = (const float*)d_in[8];
    const float* cg1   = (const float*)d_in[9];
    const float* cbe1  = (const float*)d_in[10];
    const float* cW2   = (const float*)d_in[11];
    const float* cb2   = (const float*)d_in[12];
    const float* lng   = (const float*)d_in[13];
    const float* lnb   = (const float*)d_in[14];
    const float* linW  = (const float*)d_in[15];
    const float* linb  = (const float*)d_in[16];
    const void*  ei    = d_in[17];   // int32 or int64, detected on device

    const int CONV_SMEM = (HH * HH2 + HH2 * HH + 3 * HH2 + HH + 8 * HH + 8 * HH2) * (int)sizeof(float);
    cudaFuncSetAttribute(convK, cudaFuncAttributeMaxDynamicSharedMemorySize, CONV_SMEM);

    // CSR build (per launch; deterministic counts/offsets)
    detectK<<<1, 32>>>(ei);
    zeroK<<<(NN + 255) / 256, 256>>>();
    histK<<<(EE + 255) / 256, 256>>>(ei);
    scanK<<<1, 1024>>>();
    scatterK<<<(EE + 255) / 256, 256>>>(ei);

    // encoders
    eaK<<<1184, 256>>>(eattr, edgeW, edgeb);
    nodeEncK<<<592, 256>>>(x, nodeW, nodeb);

    // layer 0: conv only (input in d_z, output to d_h)
    convK<<<444, 256, CONV_SMEM>>>(cW1, cb1, cg1, cbe1, cW2, cb2, convT, 0, 0);

    // res+ layers 1..3
    for (int l = 1; l < NLAYER; l++) {
        normReluK<<<(NN + 7) / 8, 256>>>(lng + l * HH, lnb + l * HH);
        convK<<<444, 256, CONV_SMEM>>>(cW1 + l * HH * HH2, cb1 + l * HH2,
                                       cg1 + l * HH2, cbe1 + l * HH2,
                                       cW2 + l * HH2 * HH, cb2 + l * HH,
                                       convT, l, 1);
    }

    // final projection
    finalK<<<592, 256>>>(lng, lnb, linW, linb, (float*)d_out);
}

// round 5
// speedup vs baseline: 1.6043x; 1.6043x over previous
#include <cuda_runtime.h>
#include <cuda_fp16.h>

#define NN 50000
#define EE 800000
#define IND 128
#define EDD 16
#define HH 64
#define HH2 128
#define OUTD 8
#define NLAYER 4
#define NB 196              // ceil(NN/256)
#define NGROUP (NN / 8)     // 6250 node-groups of 8

typedef unsigned long long ull;

// ---------------- scratch (static __device__, no allocations) ----------------
__device__ __half2 d_ea2[EE * 32];     // 102.4 MB: edge features fp16, dst-sorted
__device__ int   d_srcS[EE];           // src node id per sorted edge
__device__ int   d_perm[EE];           // sorted-pos -> original edge id
__device__ int   d_rowStart[NN + 1];   // CSR row offsets (by dst)
__device__ int   d_cursor[NN];         // histogram / scatter cursor
__device__ int   d_bsum[NB];
__device__ int   d_boff[NB];
__device__ float d_h[NN * HH];         // running node state
__device__ float d_z[NN * HH];         // per-layer conv input (normalized)
__device__ float d_hin[NN * HH];       // agg + root (MLP input)
__device__ int   d_is64;               // edge_index dtype flag

__device__ __forceinline__ float warpSum(float v) {
#pragma unroll
    for (int o = 16; o; o >>= 1) v += __shfl_xor_sync(0xffffffffu, v, o);
    return v;
}

// packed f32x2 helpers
__device__ __forceinline__ ull pk2(float lo, float hi) {
    ull r; asm("mov.b64 %0, {%1, %2};" : "=l"(r) : "f"(lo), "f"(hi)); return r;
}
__device__ __forceinline__ void upk2(ull v, float& lo, float& hi) {
    asm("mov.b64 {%0, %1}, %2;" : "=f"(lo), "=f"(hi) : "l"(v));
}
__device__ __forceinline__ void fma2(ull& d, ull a, ull b) {
    asm("fma.rn.f32x2 %0, %1, %2, %0;" : "+l"(d) : "l"(a), "l"(b));
}

// read edge_index entry i (0..2E-1) honoring detected dtype
__device__ __forceinline__ int eiAt(const void* eiv, int i) {
    if (d_is64) return (int)((const long long*)eiv)[i];
    return ((const int*)eiv)[i];
}

// ---------------- dtype probe ----------------
__global__ void detectK(const void* eiv) {
    if (threadIdx.x == 0 && blockIdx.x == 0) {
        const unsigned long long* p = (const unsigned long long*)eiv;
        int ok = 1;
#pragma unroll
        for (int i = 0; i < 8; i++)
            if (p[i] >= (unsigned long long)NN) ok = 0;
        d_is64 = ok;
    }
}

// ---------------- CSR build ----------------
__global__ void zeroK() {
    int i = blockIdx.x * blockDim.x + threadIdx.x;
    if (i < NN) d_cursor[i] = 0;
}

__global__ void histK(const void* eiv) {
    int e = blockIdx.x * blockDim.x + threadIdx.x;
    if (e < EE) {
        int d = eiAt(eiv, EE + e);
        if ((unsigned)d < (unsigned)NN) atomicAdd(&d_cursor[d], 1);
    }
}

__global__ void blockSumK() {
    __shared__ int s[256];
    int t = threadIdx.x;
    int i = blockIdx.x * 256 + t;
    s[t] = (i < NN) ? d_cursor[i] : 0;
    __syncthreads();
    for (int off = 128; off; off >>= 1) {
        if (t < off) s[t] += s[t + off];
        __syncthreads();
    }
    if (t == 0) d_bsum[blockIdx.x] = s[0];
}

__global__ void scanBsumK() {
    __shared__ int s[256];
    int t = threadIdx.x;
    int v = (t < NB) ? d_bsum[t] : 0;
    s[t] = v;
    __syncthreads();
    for (int off = 1; off < 256; off <<= 1) {
        int u = (t >= off) ? s[t - off] : 0;
        __syncthreads();
        s[t] += u;
        __syncthreads();
    }
    if (t < NB) d_boff[t] = s[t] - v;         // exclusive
    if (t == 255) d_rowStart[NN] = s[255];    // total
}

__global__ void rowStartK() {
    __shared__ int s[256];
    int t = threadIdx.x;
    int i = blockIdx.x * 256 + t;
    int v = (i < NN) ? d_cursor[i] : 0;
    s[t] = v;
    __syncthreads();
    for (int off = 1; off < 256; off <<= 1) {
        int u = (t >= off) ? s[t - off] : 0;
        __syncthreads();
        s[t] += u;
        __syncthreads();
    }
    int excl = s[t] - v + d_boff[blockIdx.x];
    if (i < NN) { d_rowStart[i] = excl; d_cursor[i] = excl; }
}

__global__ void scatterK(const void* eiv) {
    int e = blockIdx.x * blockDim.x + threadIdx.x;
    if (e < EE) {
        int s = eiAt(eiv, e);
        int d = eiAt(eiv, EE + e);
        if ((unsigned)d < (unsigned)NN && (unsigned)s < (unsigned)NN) {
            int p = atomicAdd(&d_cursor[d], 1);
            d_srcS[p] = s;
            d_perm[p] = e;
        }
    }
}

// ---------------- edge encoder: d_ea2[sorted] = fp16(edge_attr[perm] @ edge_W + edge_b) ----
__global__ void eaK(const float* __restrict__ eattr,
                    const float* __restrict__ eW,
                    const float* __restrict__ eb) {
    __shared__ float Ws[EDD * HH];
    __shared__ float bs[HH];
    for (int i = threadIdx.x; i < EDD * HH; i += blockDim.x) Ws[i] = eW[i];
    if (threadIdx.x < HH) bs[threadIdx.x] = eb[threadIdx.x];
    __syncthreads();
    int lane = threadIdx.x & 31;
    int warp = (blockIdx.x * blockDim.x + threadIdx.x) >> 5;
    int nwarp = (gridDim.x * blockDim.x) >> 5;
    int c = 2 * lane;
    for (int i = warp; i < EE; i += nwarp) {
        int e = d_perm[i];
        float a = (lane < EDD) ? __ldg(&eattr[e * EDD + lane]) : 0.f;
        float c0 = bs[c], c1 = bs[c + 1];
#pragma unroll
        for (int k = 0; k < EDD; k++) {
            float ak = __shfl_sync(0xffffffffu, a, k);
            float2 w = *(const float2*)&Ws[k * HH + c];
            c0 = fmaf(ak, w.x, c0);
            c1 = fmaf(ak, w.y, c1);
        }
        d_ea2[i * 32 + lane] = __floats2half2_rn(c0, c1);
    }
}

// ---------------- node encoder: d_z = x @ node_W + node_b ----------------
__global__ void nodeEncK(const float* __restrict__ x,
                         const float* __restrict__ W,
                         const float* __restrict__ b) {
    __shared__ float Ws[IND * HH];
    __shared__ float bs[HH];
    __shared__ float xs[8][IND];
    for (int i = threadIdx.x; i < IND * HH; i += blockDim.x) Ws[i] = W[i];
    if (threadIdx.x < HH) bs[threadIdx.x] = b[threadIdx.x];
    __syncthreads();
    int lane = threadIdx.x & 31, wi = threadIdx.x >> 5;
    int warp = (blockIdx.x << 3) + wi;
    int nwarp = gridDim.x << 3;
    int c = 2 * lane;
    for (int v = warp; v < NN; v += nwarp) {
        const float* xr = &x[v * IND];
        xs[wi][lane]      = xr[lane];
        xs[wi][lane + 32] = xr[lane + 32];
        xs[wi][lane + 64] = xr[lane + 64];
        xs[wi][lane + 96] = xr[lane + 96];
        __syncwarp();
        float c0 = bs[c], c1 = bs[c + 1];
#pragma unroll 8
        for (int k = 0; k < IND; k++) {
            float xk = xs[wi][k];
            float2 w = *(const float2*)&Ws[k * HH + c];
            c0 = fmaf(xk, w.x, c0);
            c1 = fmaf(xk, w.y, c1);
        }
        *(float2*)&d_z[v * HH + c] = make_float2(c0, c1);
        __syncwarp();
    }
}

// ---------------- aggregation: d_hin = softmax-agg(msg) + z ----------------
// warp per node; single-pass softmax (logits = relu(.)+eps in [1e-7,~10], exp safe in fp32)
__global__ void aggK(const float* __restrict__ tptr, int layer) {
    int lane = threadIdx.x & 31;
    int v = (blockIdx.x * blockDim.x + threadIdx.x) >> 5;
    if (v >= NN) return;
    float t = __ldg(&tptr[layer]);
    int c = 2 * lane;
    int rs = d_rowStart[v], re = d_rowStart[v + 1];
    float s0 = 0.f, s1 = 0.f, w0 = 0.f, w1 = 0.f;
    const __half2* pe = d_ea2 + (size_t)rs * 32 + lane;
    for (int e = rs; e < re; e++, pe += 32) {
        float2 eav = __half22float2(__ldcs(pe));
        int u = __ldg(&d_srcS[e]);
        float2 zu = *(const float2*)&d_z[u * HH + c];
        float m0 = fmaxf(zu.x + eav.x, 0.f) + 1e-7f;
        float m1 = fmaxf(zu.y + eav.y, 0.f) + 1e-7f;
        float p0 = __expf(m0 * t);
        float p1 = __expf(m1 * t);
        s0 += p0; s1 += p1;
        w0 = fmaf(m0, p0, w0);
        w1 = fmaf(m1, p1, w1);
    }
    float2 zv = *(const float2*)&d_z[v * HH + c];
    float h0 = w0 / (s0 + 1e-16f) + zv.x;
    float h1 = w1 / (s1 + 1e-16f) + zv.y;
    *(float2*)&d_hin[v * HH + c] = make_float2(h0, h1);
}

// ---------------- MLP: h = [res +] MLP2(relu(LN(MLP1(hin)))) ; optional z_next -------------
// 8 warps/block; each warp batches 8 nodes; f32x2 packed FMA over node-pairs.
// smem: W1(8192) W2(8192) b1/g1/be1(384) b2(64) gn(64) bn(64) + 8*1280 staging
#define MLP_SMEM ((8192 + 8192 + 384 + 64 + 64 + 64 + 8 * 1280) * 4)

__global__ void mlpK(const float* __restrict__ W1, const float* __restrict__ b1,
                     const float* __restrict__ g1, const float* __restrict__ be1,
                     const float* __restrict__ W2, const float* __restrict__ b2,
                     const float* __restrict__ gn, const float* __restrict__ bn,
                     int residual, int writeZ) {
    extern __shared__ float sm[];
    float* W1s  = sm;                 // 8192
    float* W2s  = W1s + 8192;         // 8192
    float* b1s  = W2s + 8192;         // 128
    float* g1s  = b1s + 128;          // 128
    float* be1s = g1s + 128;          // 128
    float* b2s  = be1s + 128;         // 64
    float* gns  = b2s + 64;           // 64
    float* bns  = gns + 64;           // 64
    float* sball = bns + 64;          // 8 * 1280

    for (int i = threadIdx.x; i < 8192; i += blockDim.x) { W1s[i] = W1[i]; W2s[i] = W2[i]; }
    for (int i = threadIdx.x; i < 128; i += blockDim.x) { b1s[i] = b1[i]; g1s[i] = g1[i]; be1s[i] = be1[i]; }
    if (threadIdx.x < 64) {
        b2s[threadIdx.x] = b2[threadIdx.x];
        if (writeZ) { gns[threadIdx.x] = gn[threadIdx.x]; bns[threadIdx.x] = bn[threadIdx.x]; }
    }
    __syncthreads();

    int lane = threadIdx.x & 31, wid = threadIdx.x >> 5;
    float* sb = sball + wid * 1280;
    int o = lane * 4;      // MLP1 output cols [o, o+4)
    int c2 = lane * 2;     // MLP2 output cols [c2, c2+2)

    for (int g = blockIdx.x * 8 + wid; g < NGROUP; g += gridDim.x * 8) {
        int vbase = g * 8;

        // stage h: sb[k*10 + n] = hin[vbase+n][k]
        const float* hp = d_hin + (size_t)vbase * HH;
        for (int i = lane; i < 512; i += 32) {
            int n = i >> 6, k = i & 63;
            sb[k * 10 + n] = hp[i];
        }
        __syncwarp();

        // ---- MLP1: 64 -> 128, 4 node-pairs x 4 outputs, packed f32x2 ----
        ull acc[4][4];
#pragma unroll
        for (int j = 0; j < 4; j++) {
            ull bj = pk2(b1s[o + j], b1s[o + j]);
#pragma unroll
            for (int p = 0; p < 4; p++) acc[p][j] = bj;
        }
#pragma unroll 8
        for (int k = 0; k < 64; k++) {
            float4 w = *(const float4*)&W1s[k * 128 + o];
            ull wd0 = pk2(w.x, w.x), wd1 = pk2(w.y, w.y);
            ull wd2 = pk2(w.z, w.z), wd3 = pk2(w.w, w.w);
#pragma unroll
            for (int p = 0; p < 4; p++) {
                ull hpair = *(const ull*)&sb[k * 10 + 2 * p];
                fma2(acc[p][0], hpair, wd0);
                fma2(acc[p][1], hpair, wd1);
                fma2(acc[p][2], hpair, wd2);
                fma2(acc[p][3], hpair, wd3);
            }
        }
        __syncwarp();

        // ---- LayerNorm(128) + relu, write z into sb[k2*10 + n] ----
#pragma unroll
        for (int p = 0; p < 4; p++) {
            float a0[4], a1[4];
#pragma unroll
            for (int j = 0; j < 4; j++) upk2(acc[p][j], a0[j], a1[j]);
            float mu0 = warpSum(a0[0] + a0[1] + a0[2] + a0[3]) * (1.f / HH2);
            float mu1 = warpSum(a1[0] + a1[1] + a1[2] + a1[3]) * (1.f / HH2);
            float dv0 = 0.f, dv1 = 0.f;
#pragma unroll
            for (int j = 0; j < 4; j++) {
                a0[j] -= mu0; a1[j] -= mu1;
                dv0 = fmaf(a0[j], a0[j], dv0);
                dv1 = fmaf(a1[j], a1[j], dv1);
            }
            float inv0 = rsqrtf(warpSum(dv0) * (1.f / HH2) + 1e-5f);
            float inv1 = rsqrtf(warpSum(dv1) * (1.f / HH2) + 1e-5f);
#pragma unroll
            for (int j = 0; j < 4; j++) {
                float z0 = fmaxf(fmaf(a0[j] * inv0, g1s[o + j], be1s[o + j]), 0.f);
                float z1 = fmaxf(fmaf(a1[j] * inv1, g1s[o + j], be1s[o + j]), 0.f);
                *(ull*)&sb[(o + j) * 10 + 2 * p] = pk2(z0, z1);
            }
        }
        __syncwarp();

        // ---- MLP2: 128 -> 64, 4 node-pairs x 2 outputs ----
        ull oa[4][2];
        {
            ull bb0 = pk2(b2s[c2], b2s[c2]);
            ull bb1 = pk2(b2s[c2 + 1], b2s[c2 + 1]);
#pragma unroll
            for (int p = 0; p < 4; p++) { oa[p][0] = bb0; oa[p][1] = bb1; }
        }
#pragma unroll 8
        for (int k = 0; k < 128; k++) {
            float2 w = *(const float2*)&W2s[k * 64 + c2];
            ull wd0 = pk2(w.x, w.x), wd1 = pk2(w.y, w.y);
#pragma unroll
            for (int p = 0; p < 4; p++) {
                ull zp = *(const ull*)&sb[k * 10 + 2 * p];
                fma2(oa[p][0], zp, wd0);
                fma2(oa[p][1], zp, wd1);
            }
        }

        // ---- epilogue: residual, store d_h, optional z_next = relu(LN(h)) ----
#pragma unroll
        for (int p = 0; p < 4; p++) {
            float o00, o10, o01, o11;
            upk2(oa[p][0], o00, o10);   // output col c2   : nodes 2p, 2p+1
            upk2(oa[p][1], o01, o11);   // output col c2+1
#pragma unroll
            for (int e = 0; e < 2; e++) {
                int v = vbase + 2 * p + e;
                float h0 = e ? o10 : o00;
                float h1 = e ? o11 : o01;
                if (residual) {
                    float2 hv = *(const float2*)&d_h[(size_t)v * HH + c2];
                    h0 += hv.x; h1 += hv.y;
                }
                *(float2*)&d_h[(size_t)v * HH + c2] = make_float2(h0, h1);
                if (writeZ) {
                    float mu = warpSum(h0 + h1) * (1.f / HH);
                    float d0 = h0 - mu, d1 = h1 - mu;
                    float var = warpSum(d0 * d0 + d1 * d1) * (1.f / HH);
                    float inv = rsqrtf(var + 1e-5f);
                    float z0 = fmaxf(fmaf(d0 * inv, gns[c2], bns[c2]), 0.f);
                    float z1 = fmaxf(fmaf(d1 * inv, gns[c2 + 1], bns[c2 + 1]), 0.f);
                    *(float2*)&d_z[(size_t)v * HH + c2] = make_float2(z0, z1);
                }
            }
        }
        __syncwarp();
    }
}

// ---------------- final: out = relu(LN(d_h, g0, b0)) @ lin_W + lin_b ----------------
__global__ void finalK(const float* __restrict__ g, const float* __restrict__ b,
                       const float* __restrict__ lW, const float* __restrict__ lb,
                       float* __restrict__ out) {
    __shared__ float Ws[HH * OUTD];
    __shared__ float zs[8][HH];
    for (int i = threadIdx.x; i < HH * OUTD; i += blockDim.x) Ws[i] = lW[i];
    __syncthreads();
    int lane = threadIdx.x & 31, wi = threadIdx.x >> 5;
    int warp = (blockIdx.x << 3) + wi;
    int nwarp = gridDim.x << 3;
    int c = 2 * lane;
    for (int v = warp; v < NN; v += nwarp) {
        float2 hv = *(const float2*)&d_h[v * HH + c];
        float mu = warpSum(hv.x + hv.y) * (1.f / HH);
        float d0 = hv.x - mu, d1 = hv.y - mu;
        float var = warpSum(d0 * d0 + d1 * d1) * (1.f / HH);
        float inv = rsqrtf(var + 1e-5f);
        zs[wi][c]     = fmaxf(fmaf(d0 * inv, __ldg(&g[c]),     __ldg(&b[c])),     0.f);
        zs[wi][c + 1] = fmaxf(fmaf(d1 * inv, __ldg(&g[c + 1]), __ldg(&b[c + 1])), 0.f);
        __syncwarp();
        if (lane < OUTD) {
            float acc = __ldg(&lb[lane]);
#pragma unroll
            for (int k = 0; k < HH; k++) acc = fmaf(zs[wi][k], Ws[k * OUTD + lane], acc);
            out[v * OUTD + lane] = acc;
        }
        __syncwarp();
    }
}

// ---------------- launch ----------------
extern "C" void kernel_launch(void* const* d_in, const int* in_sizes, int n_in,
                              void* d_out, int out_size) {
    const float* x     = (const float*)d_in[0];
    const float* eattr = (const float*)d_in[1];
    const float* nodeW = (const float*)d_in[2];
    const float* nodeb = (const float*)d_in[3];
    const float* edgeW = (const float*)d_in[4];
    const float* edgeb = (const float*)d_in[5];
    const float* convT = (const float*)d_in[6];
    const float* cW1   = (const float*)d_in[7];
    const float* cb1   = (const float*)d_in[8];
    const float* cg1   = (const float*)d_in[9];
    const float* cbe1  = (const float*)d_in[10];
    const float* cW2   = (const float*)d_in[11];
    const float* cb2   = (const float*)d_in[12];
    const float* lng   = (const float*)d_in[13];
    const float* lnb   = (const float*)d_in[14];
    const float* linW  = (const float*)d_in[15];
    const float* linb  = (const float*)d_in[16];
    const void*  ei    = d_in[17];   // int32 or int64, detected on device

    cudaFuncSetAttribute(mlpK, cudaFuncAttributeMaxDynamicSharedMemorySize, MLP_SMEM);

    // CSR build
    detectK<<<1, 32>>>(ei);
    zeroK<<<(NN + 255) / 256, 256>>>();
    histK<<<(EE + 255) / 256, 256>>>(ei);
    blockSumK<<<NB, 256>>>();
    scanBsumK<<<1, 256>>>();
    rowStartK<<<NB, 256>>>();
    scatterK<<<(EE + 255) / 256, 256>>>(ei);

    // encoders
    eaK<<<1184, 256>>>(eattr, edgeW, edgeb);
    nodeEncK<<<592, 256>>>(x, nodeW, nodeb);

    // layers
    for (int l = 0; l < NLAYER; l++) {
        aggK<<<(NN * 32 + 255) / 256, 256>>>(convT, l);
        int writeZ = (l < NLAYER - 1);
        const float* gn = writeZ ? (lng + (l + 1) * HH) : lng;
        const float* bn = writeZ ? (lnb + (l + 1) * HH) : lnb;
        mlpK<<<296, 256, MLP_SMEM>>>(cW1 + l * HH * HH2, cb1 + l * HH2,
                                     cg1 + l * HH2, cbe1 + l * HH2,
                                     cW2 + l * HH2 * HH, cb2 + l * HH,
                                     gn, bn, (l > 0) ? 1 : 0, writeZ);
    }

    // final projection (LN with layer-0 params)
    finalK<<<592, 256>>>(lng, lnb, linW, linb, (float*)d_out);
}

// round 6
// speedup vs baseline: 1.9183x; 1.1957x over previous
#include <cuda_runtime.h>
#include <cuda_fp16.h>

#define NN 50000
#define EE 800000
#define IND 128
#define EDD 16
#define HH 64
#define HH2 128
#define OUTD 8
#define NLAYER 4
#define NB 196              // ceil(NN/256)
#define NGROUP (NN / 8)     // 6250 node-groups of 8

typedef unsigned long long ull;
typedef long long ll;

// ---------------- scratch (static __device__, no allocations) ----------------
__device__ __half2 d_ea2[EE * 32];     // 102.4 MB: edge features fp16, dst-sorted
__device__ int2  d_sp[EE];             // per sorted edge: {src node, original edge id}
__device__ int   d_rowStart[NN + 1];   // CSR row offsets (by dst)
__device__ int   d_cursor[NN];         // histogram / scatter cursor (left zeroed for next replay)
__device__ int   d_bsum[NB];
__device__ float d_h[NN * HH];         // running node state
__device__ float d_z[NN * HH];         // conv input fp32 (root term)
__device__ __half2 d_z2[NN * 32];      // conv input fp16 (gather term)
__device__ float d_hin[NN * HH];       // agg + root (MLP input)

__device__ __forceinline__ float warpSum(float v) {
#pragma unroll
    for (int o = 16; o; o >>= 1) v += __shfl_xor_sync(0xffffffffu, v, o);
    return v;
}

// packed f32x2 helpers
__device__ __forceinline__ ull pk2(float lo, float hi) {
    ull r; asm("mov.b64 %0, {%1, %2};" : "=l"(r) : "f"(lo), "f"(hi)); return r;
}
__device__ __forceinline__ void upk2(ull v, float& lo, float& hi) {
    asm("mov.b64 {%0, %1}, %2;" : "=f"(lo), "=f"(hi) : "l"(v));
}
__device__ __forceinline__ void fma2(ull& d, ull a, ull b) {
    asm("fma.rn.f32x2 %0, %1, %2, %0;" : "+l"(d) : "l"(a), "l"(b));
}

// per-block dtype probe: int64 data has high words 0 -> first 8 ull all < NN
__device__ __forceinline__ int probe64(const void* eiv) {
    const ull* p = (const ull*)eiv;
    int ok = 1;
#pragma unroll
    for (int i = 0; i < 8; i++)
        if (p[i] >= (ull)NN) ok = 0;
    return ok;
}

// ---------------- CSR build ----------------
__global__ void histK(const void* eiv) {
    __shared__ int is64s;
    if (threadIdx.x == 0) is64s = probe64(eiv);
    __syncthreads();
    int e = blockIdx.x * blockDim.x + threadIdx.x;
    if (e < EE) {
        int d = is64s ? (int)((const ll*)eiv)[EE + e] : ((const int*)eiv)[EE + e];
        if ((unsigned)d < (unsigned)NN) atomicAdd(&d_cursor[d], 1);
    }
}

__global__ void blockSumK() {
    __shared__ int s[256];
    int t = threadIdx.x;
    int i = blockIdx.x * 256 + t;
    s[t] = (i < NN) ? d_cursor[i] : 0;
    __syncthreads();
    for (int off = 128; off; off >>= 1) {
        if (t < off) s[t] += s[t + off];
        __syncthreads();
    }
    if (t == 0) d_bsum[blockIdx.x] = s[0];
}

// each block: scan the 196 block sums locally (redundant, cheap) + scan its own 256 counts
__global__ void rowStartK() {
    __shared__ int bsc[256];
    __shared__ int s[256];
    int t = threadIdx.x;
    int bv = (t < NB) ? d_bsum[t] : 0;
    bsc[t] = bv;
    __syncthreads();
    for (int off = 1; off < 256; off <<= 1) {
        int u = (t >= off) ? bsc[t - off] : 0;
        __syncthreads();
        bsc[t] += u;
        __syncthreads();
    }
    int boff = (blockIdx.x == 0) ? 0 : bsc[blockIdx.x - 1];
    if (blockIdx.x == 0 && t == 0) d_rowStart[NN] = bsc[255];

    int i = blockIdx.x * 256 + t;
    int v = (i < NN) ? d_cursor[i] : 0;
    s[t] = v;
    __syncthreads();
    for (int off = 1; off < 256; off <<= 1) {
        int u = (t >= off) ? s[t - off] : 0;
        __syncthreads();
        s[t] += u;
        __syncthreads();
    }
    int excl = s[t] - v + boff;
    if (i < NN) { d_rowStart[i] = excl; d_cursor[i] = excl; }
}

__global__ void scatterK(const void* eiv) {
    __shared__ int is64s;
    if (threadIdx.x == 0) is64s = probe64(eiv);
    __syncthreads();
    int e = blockIdx.x * blockDim.x + threadIdx.x;
    if (e < EE) {
        int s, d;
        if (is64s) { s = (int)((const ll*)eiv)[e]; d = (int)((const ll*)eiv)[EE + e]; }
        else       { s = ((const int*)eiv)[e];     d = ((const int*)eiv)[EE + e]; }
        if ((unsigned)d < (unsigned)NN && (unsigned)s < (unsigned)NN) {
            int p = atomicAdd(&d_cursor[d], 1);
            d_sp[p] = make_int2(s, e);
        }
    }
}

// ---------------- edge encoder: thread-per-sorted-edge, packed f32x2, coalesced out ----
// Also zeroes d_cursor for the next replay (runs after scatter).
__global__ void eaK(const float* __restrict__ eattr,
                    const float* __restrict__ eW,
                    const float* __restrict__ eb) {
    __shared__ float Ws[EDD * HH];      // 4KB
    __shared__ float bsm[HH];
    __shared__ unsigned st[256 * 33];   // padded half2 staging, 33.8KB
    int t = threadIdx.x;
    for (int i = t; i < EDD * HH; i += 256) Ws[i] = eW[i];
    if (t < HH) bsm[t] = eb[t];
    if (blockIdx.x < NB) {
        int ci = blockIdx.x * 256 + t;
        if (ci < NN) d_cursor[ci] = 0;
    }
    __syncthreads();

    int base = blockIdx.x * 256;        // grid = EE/256 exactly
    int e = d_sp[base + t].y;
    const float4* ap = (const float4*)(eattr + (size_t)e * EDD);
    float4 a0 = __ldg(ap), a1 = __ldg(ap + 1), a2 = __ldg(ap + 2), a3 = __ldg(ap + 3);
    float att[16] = { a0.x, a0.y, a0.z, a0.w, a1.x, a1.y, a1.z, a1.w,
                      a2.x, a2.y, a2.z, a2.w, a3.x, a3.y, a3.z, a3.w };

#pragma unroll
    for (int cb = 0; cb < HH; cb += 32) {
        ull acc[16];
#pragma unroll
        for (int j = 0; j < 16; j++) acc[j] = pk2(bsm[cb + 2 * j], bsm[cb + 2 * j + 1]);
#pragma unroll
        for (int k = 0; k < EDD; k++) {
            ull ak = pk2(att[k], att[k]);
            const ull* wrow = (const ull*)&Ws[k * HH + cb];
#pragma unroll
            for (int j = 0; j < 16; j++) fma2(acc[j], ak, wrow[j]);
        }
#pragma unroll
        for (int j = 0; j < 16; j++) {
            float lo, hi; upk2(acc[j], lo, hi);
            __half2 hv = __floats2half2_rn(lo, hi);
            st[t * 33 + (cb >> 1) + j] = *reinterpret_cast<unsigned*>(&hv);
        }
    }
    __syncthreads();

    unsigned* gout = (unsigned*)(d_ea2 + (size_t)base * 32);
    for (int idx = t; idx < 256 * 32; idx += 256) {
        int r = idx >> 5, c = idx & 31;
        gout[idx] = st[r * 33 + c];
    }
}

// ---------------- node encoder: d_z/d_z2 = x @ node_W + node_b ----------------
__global__ void nodeEncK(const float* __restrict__ x,
                         const float* __restrict__ W,
                         const float* __restrict__ b) {
    __shared__ float Ws[IND * HH];
    __shared__ float bs[HH];
    __shared__ float xs[8][IND];
    for (int i = threadIdx.x; i < IND * HH; i += blockDim.x) Ws[i] = W[i];
    if (threadIdx.x < HH) bs[threadIdx.x] = b[threadIdx.x];
    __syncthreads();
    int lane = threadIdx.x & 31, wi = threadIdx.x >> 5;
    int warp = (blockIdx.x << 3) + wi;
    int nwarp = gridDim.x << 3;
    int c = 2 * lane;
    for (int v = warp; v < NN; v += nwarp) {
        const float* xr = &x[(size_t)v * IND];
        xs[wi][lane]      = xr[lane];
        xs[wi][lane + 32] = xr[lane + 32];
        xs[wi][lane + 64] = xr[lane + 64];
        xs[wi][lane + 96] = xr[lane + 96];
        __syncwarp();
        float c0 = bs[c], c1 = bs[c + 1];
#pragma unroll 8
        for (int k = 0; k < IND; k++) {
            float xk = xs[wi][k];
            float2 w = *(const float2*)&Ws[k * HH + c];
            c0 = fmaf(xk, w.x, c0);
            c1 = fmaf(xk, w.y, c1);
        }
        *(float2*)&d_z[(size_t)v * HH + c] = make_float2(c0, c1);
        d_z2[(size_t)v * 32 + lane] = __floats2half2_rn(c0, c1);
        __syncwarp();
    }
}

// ---------------- aggregation: d_hin = softmax-agg(msg) + z ----------------
// warp per node; single-pass softmax (logits = relu(.)+eps in [1e-7,~10], exp safe in fp32)
__global__ void aggK(const float* __restrict__ tptr, int layer) {
    int lane = threadIdx.x & 31;
    int v = (blockIdx.x * blockDim.x + threadIdx.x) >> 5;
    if (v >= NN) return;
    float t = __ldg(&tptr[layer]);
    int rs = d_rowStart[v], re = d_rowStart[v + 1];
    float s0 = 0.f, s1 = 0.f, w0 = 0.f, w1 = 0.f;
    const __half2* pe = d_ea2 + (size_t)rs * 32 + lane;
    const __half2 zero2 = __float2half2_rn(0.f);
    int e = rs;
    for (; e + 2 <= re; e += 2, pe += 64) {
        __half2 ea0 = __ldcs(pe);
        __half2 ea1 = __ldcs(pe + 32);
        int u0 = __ldg(&d_sp[e].x);
        int u1 = __ldg(&d_sp[e + 1].x);
        __half2 z0 = d_z2[(size_t)u0 * 32 + lane];
        __half2 z1 = d_z2[(size_t)u1 * 32 + lane];
        float2 mA = __half22float2(__hmax2(__hadd2(z0, ea0), zero2));
        float2 mB = __half22float2(__hmax2(__hadd2(z1, ea1), zero2));
        float m0 = mA.x + 1e-7f, m1 = mA.y + 1e-7f;
        float m2 = mB.x + 1e-7f, m3 = mB.y + 1e-7f;
        float p0 = __expf(m0 * t), p1 = __expf(m1 * t);
        float p2 = __expf(m2 * t), p3 = __expf(m3 * t);
        s0 += p0 + p2; s1 += p1 + p3;
        w0 = fmaf(m0, p0, w0); w0 = fmaf(m2, p2, w0);
        w1 = fmaf(m1, p1, w1); w1 = fmaf(m3, p3, w1);
    }
    if (e < re) {
        __half2 ea0 = __ldcs(pe);
        int u0 = __ldg(&d_sp[e].x);
        __half2 z0 = d_z2[(size_t)u0 * 32 + lane];
        float2 mA = __half22float2(__hmax2(__hadd2(z0, ea0), zero2));
        float m0 = mA.x + 1e-7f, m1 = mA.y + 1e-7f;
        float p0 = __expf(m0 * t), p1 = __expf(m1 * t);
        s0 += p0; s1 += p1;
        w0 = fmaf(m0, p0, w0);
        w1 = fmaf(m1, p1, w1);
    }
    int c = 2 * lane;
    float2 zv = *(const float2*)&d_z[(size_t)v * HH + c];
    float h0 = w0 / (s0 + 1e-16f) + zv.x;
    float h1 = w1 / (s1 + 1e-16f) + zv.y;
    *(float2*)&d_hin[(size_t)v * HH + c] = make_float2(h0, h1);
}

// ---------------- MLP: h = [res +] MLP2(relu(LN(MLP1(hin)))) ; optional z_next -------------
// 8 warps/block; each warp batches 8 nodes; f32x2 packed FMA over node-pairs.
#define MLP_SMEM ((8192 + 8192 + 384 + 64 + 64 + 64 + 8 * 1280) * 4)

__global__ void mlpK(const float* __restrict__ W1, const float* __restrict__ b1,
                     const float* __restrict__ g1, const float* __restrict__ be1,
                     const float* __restrict__ W2, const float* __restrict__ b2,
                     const float* __restrict__ gn, const float* __restrict__ bn,
                     int residual, int writeZ) {
    extern __shared__ float sm[];
    float* W1s  = sm;                 // 8192
    float* W2s  = W1s + 8192;         // 8192
    float* b1s  = W2s + 8192;         // 128
    float* g1s  = b1s + 128;          // 128
    float* be1s = g1s + 128;          // 128
    float* b2s  = be1s + 128;         // 64
    float* gns  = b2s + 64;           // 64
    float* bns  = gns + 64;           // 64
    float* sball = bns + 64;          // 8 * 1280

    for (int i = threadIdx.x; i < 8192; i += blockDim.x) { W1s[i] = W1[i]; W2s[i] = W2[i]; }
    for (int i = threadIdx.x; i < 128; i += blockDim.x) { b1s[i] = b1[i]; g1s[i] = g1[i]; be1s[i] = be1[i]; }
    if (threadIdx.x < 64) {
        b2s[threadIdx.x] = b2[threadIdx.x];
        if (writeZ) { gns[threadIdx.x] = gn[threadIdx.x]; bns[threadIdx.x] = bn[threadIdx.x]; }
    }
    __syncthreads();

    int lane = threadIdx.x & 31, wid = threadIdx.x >> 5;
    float* sb = sball + wid * 1280;
    int o = lane * 4;      // MLP1 output cols [o, o+4)
    int c2 = lane * 2;     // MLP2 output cols [c2, c2+2)

    for (int g = blockIdx.x * 8 + wid; g < NGROUP; g += gridDim.x * 8) {
        int vbase = g * 8;

        // stage h: sb[k*10 + n] = hin[vbase+n][k]
        const float* hp = d_hin + (size_t)vbase * HH;
        for (int i = lane; i < 512; i += 32) {
            int n = i >> 6, k = i & 63;
            sb[k * 10 + n] = hp[i];
        }
        __syncwarp();

        // ---- MLP1: 64 -> 128, 4 node-pairs x 4 outputs, packed f32x2 ----
        ull acc[4][4];
#pragma unroll
        for (int j = 0; j < 4; j++) {
            ull bj = pk2(b1s[o + j], b1s[o + j]);
#pragma unroll
            for (int p = 0; p < 4; p++) acc[p][j] = bj;
        }
#pragma unroll 8
        for (int k = 0; k < 64; k++) {
            float4 w = *(const float4*)&W1s[k * 128 + o];
            ull wd0 = pk2(w.x, w.x), wd1 = pk2(w.y, w.y);
            ull wd2 = pk2(w.z, w.z), wd3 = pk2(w.w, w.w);
#pragma unroll
            for (int p = 0; p < 4; p++) {
                ull hpair = *(const ull*)&sb[k * 10 + 2 * p];
                fma2(acc[p][0], hpair, wd0);
                fma2(acc[p][1], hpair, wd1);
                fma2(acc[p][2], hpair, wd2);
                fma2(acc[p][3], hpair, wd3);
            }
        }
        __syncwarp();

        // ---- LayerNorm(128) + relu, write z into sb[k2*10 + n] ----
#pragma unroll
        for (int p = 0; p < 4; p++) {
            float a0[4], a1[4];
#pragma unroll
            for (int j = 0; j < 4; j++) upk2(acc[p][j], a0[j], a1[j]);
            float mu0 = warpSum(a0[0] + a0[1] + a0[2] + a0[3]) * (1.f / HH2);
            float mu1 = warpSum(a1[0] + a1[1] + a1[2] + a1[3]) * (1.f / HH2);
            float dv0 = 0.f, dv1 = 0.f;
#pragma unroll
            for (int j = 0; j < 4; j++) {
                a0[j] -= mu0; a1[j] -= mu1;
                dv0 = fmaf(a0[j], a0[j], dv0);
                dv1 = fmaf(a1[j], a1[j], dv1);
            }
            float inv0 = rsqrtf(warpSum(dv0) * (1.f / HH2) + 1e-5f);
            float inv1 = rsqrtf(warpSum(dv1) * (1.f / HH2) + 1e-5f);
#pragma unroll
            for (int j = 0; j < 4; j++) {
                float z0 = fmaxf(fmaf(a0[j] * inv0, g1s[o + j], be1s[o + j]), 0.f);
                float z1 = fmaxf(fmaf(a1[j] * inv1, g1s[o + j], be1s[o + j]), 0.f);
                *(ull*)&sb[(o + j) * 10 + 2 * p] = pk2(z0, z1);
            }
        }
        __syncwarp();

        // ---- MLP2: 128 -> 64, 4 node-pairs x 2 outputs ----
        ull oa[4][2];
        {
            ull bb0 = pk2(b2s[c2], b2s[c2]);
            ull bb1 = pk2(b2s[c2 + 1], b2s[c2 + 1]);
#pragma unroll
            for (int p = 0; p < 4; p++) { oa[p][0] = bb0; oa[p][1] = bb1; }
        }
#pragma unroll 8
        for (int k = 0; k < 128; k++) {
            float2 w = *(const float2*)&W2s[k * 64 + c2];
            ull wd0 = pk2(w.x, w.x), wd1 = pk2(w.y, w.y);
#pragma unroll
            for (int p = 0; p < 4; p++) {
                ull zp = *(const ull*)&sb[k * 10 + 2 * p];
                fma2(oa[p][0], zp, wd0);
                fma2(oa[p][1], zp, wd1);
            }
        }

        // ---- epilogue: residual, store d_h, optional z_next = relu(LN(h)) ----
#pragma unroll
        for (int p = 0; p < 4; p++) {
            float o00, o10, o01, o11;
            upk2(oa[p][0], o00, o10);   // output col c2   : nodes 2p, 2p+1
            upk2(oa[p][1], o01, o11);   // output col c2+1
#pragma unroll
            for (int e = 0; e < 2; e++) {
                int v = vbase + 2 * p + e;
                float h0 = e ? o10 : o00;
                float h1 = e ? o11 : o01;
                if (residual) {
                    float2 hv = *(const float2*)&d_h[(size_t)v * HH + c2];
                    h0 += hv.x; h1 += hv.y;
                }
                *(float2*)&d_h[(size_t)v * HH + c2] = make_float2(h0, h1);
                if (writeZ) {
                    float mu = warpSum(h0 + h1) * (1.f / HH);
                    float d0 = h0 - mu, d1 = h1 - mu;
                    float var = warpSum(d0 * d0 + d1 * d1) * (1.f / HH);
                    float inv = rsqrtf(var + 1e-5f);
                    float z0 = fmaxf(fmaf(d0 * inv, gns[c2], bns[c2]), 0.f);
                    float z1 = fmaxf(fmaf(d1 * inv, gns[c2 + 1], bns[c2 + 1]), 0.f);
                    *(float2*)&d_z[(size_t)v * HH + c2] = make_float2(z0, z1);
                    d_z2[(size_t)v * 32 + lane] = __floats2half2_rn(z0, z1);
                }
            }
        }
        __syncwarp();
    }
}

// ---------------- final: out = relu(LN(d_h, g0, b0)) @ lin_W + lin_b ----------------
__global__ void finalK(const float* __restrict__ g, const float* __restrict__ b,
                       const float* __restrict__ lW, const float* __restrict__ lb,
                       float* __restrict__ out) {
    __shared__ float Ws[HH * OUTD];
    __shared__ float zs[8][HH];
    for (int i = threadIdx.x; i < HH * OUTD; i += blockDim.x) Ws[i] = lW[i];
    __syncthreads();
    int lane = threadIdx.x & 31, wi = threadIdx.x >> 5;
    int warp = (blockIdx.x << 3) + wi;
    int nwarp = gridDim.x << 3;
    int c = 2 * lane;
    for (int v = warp; v < NN; v += nwarp) {
        float2 hv = *(const float2*)&d_h[(size_t)v * HH + c];
        float mu = warpSum(hv.x + hv.y) * (1.f / HH);
        float d0 = hv.x - mu, d1 = hv.y - mu;
        float var = warpSum(d0 * d0 + d1 * d1) * (1.f / HH);
        float inv = rsqrtf(var + 1e-5f);
        zs[wi][c]     = fmaxf(fmaf(d0 * inv, __ldg(&g[c]),     __ldg(&b[c])),     0.f);
        zs[wi][c + 1] = fmaxf(fmaf(d1 * inv, __ldg(&g[c + 1]), __ldg(&b[c + 1])), 0.f);
        __syncwarp();
        if (lane < OUTD) {
            float acc = __ldg(&lb[lane]);
#pragma unroll
            for (int k = 0; k < HH; k++) acc = fmaf(zs[wi][k], Ws[k * OUTD + lane], acc);
            out[(size_t)v * OUTD + lane] = acc;
        }
        __syncwarp();
    }
}

// ---------------- launch ----------------
extern "C" void kernel_launch(void* const* d_in, const int* in_sizes, int n_in,
                              void* d_out, int out_size) {
    const float* x     = (const float*)d_in[0];
    const float* eattr = (const float*)d_in[1];
    const float* nodeW = (const float*)d_in[2];
    const float* nodeb = (const float*)d_in[3];
    const float* edgeW = (const float*)d_in[4];
    const float* edgeb = (const float*)d_in[5];
    const float* convT = (const float*)d_in[6];
    const float* cW1   = (const float*)d_in[7];
    const float* cb1   = (const float*)d_in[8];
    const float* cg1   = (const float*)d_in[9];
    const float* cbe1  = (const float*)d_in[10];
    const float* cW2   = (const float*)d_in[11];
    const float* cb2   = (const float*)d_in[12];
    const float* lng   = (const float*)d_in[13];
    const float* lnb   = (const float*)d_in[14];
    const float* linW  = (const float*)d_in[15];
    const float* linb  = (const float*)d_in[16];
    const void*  ei    = d_in[17];   // int32 or int64, probed on device per block

    cudaFuncSetAttribute(mlpK, cudaFuncAttributeMaxDynamicSharedMemorySize, MLP_SMEM);

    // CSR build (cursor zeroed by previous replay's eaK; globals start zero-initialized)
    histK<<<(EE + 255) / 256, 256>>>(ei);
    blockSumK<<<NB, 256>>>();
    rowStartK<<<NB, 256>>>();
    scatterK<<<(EE + 255) / 256, 256>>>(ei);          // launch #4 (profiled)

    // encoders
    eaK<<<EE / 256, 256>>>(eattr, edgeW, edgeb);       // also zeroes d_cursor
    nodeEncK<<<592, 256>>>(x, nodeW, nodeb);

    // layers
    for (int l = 0; l < NLAYER; l++) {
        aggK<<<(NN * 32 + 255) / 256, 256>>>(convT, l);
        int writeZ = (l < NLAYER - 1);
        const float* gn = writeZ ? (lng + (l + 1) * HH) : lng;
        const float* bn = writeZ ? (lnb + (l + 1) * HH) : lnb;
        mlpK<<<296, 256, MLP_SMEM>>>(cW1 + l * HH * HH2, cb1 + l * HH2,
                                     cg1 + l * HH2, cbe1 + l * HH2,
                                     cW2 + l * HH2 * HH, cb2 + l * HH,
                                     gn, bn, (l > 0) ? 1 : 0, writeZ);
    }

    // final projection (LN with layer-0 params)
    finalK<<<592, 256>>>(lng, lnb, linW, linb, (float*)d_out);
}